// round 1
// baseline (speedup 1.0000x reference)
#include <cuda_runtime.h>
#include <math.h>

// Problem constants (fixed for this problem instance)
#define NTOK 8192
#define DDIM 2048
#define HDIM 1024
#define NEXP 8
#define SHDIM 2048
#define CAP  17408   // 16384 slots + 8*128 padding headroom

// -------- scratch (device globals: allocation-free) --------
__device__ int   g_count[NEXP];
__device__ int   g_cursor[NEXP];
__device__ int   g_pbase[NEXP + 1];
__device__ int   g_tok_eid[NTOK * 2];
__device__ float g_tok_gate[NTOK * 2];
__device__ int   g_slot_tok[CAP];
__device__ float g_slot_gate[CAP];
__device__ float g_hbuf[(size_t)CAP * HDIM];     // ~71 MB
__device__ float g_hs[(size_t)NTOK * SHDIM];     // ~67 MB

// ============================================================
// 0) zero counters
// ============================================================
__global__ void k_zero() {
    if (threadIdx.x < NEXP) g_count[threadIdx.x] = 0;
}

// ============================================================
// 1) gating: logits = x @ gate_w, top-2, softmax over the 2
//    one warp per token
// ============================================================
__global__ void k_gate(const float* __restrict__ x, const float* __restrict__ gw) {
    int warp = threadIdx.x >> 5;
    int lane = threadIdx.x & 31;
    int tok = blockIdx.x * 8 + warp;
    const float* xr = x + (size_t)tok * DDIM;
    float acc[8] = {0.f,0.f,0.f,0.f,0.f,0.f,0.f,0.f};
    for (int d = lane; d < DDIM; d += 32) {
        float xv = xr[d];
        float4 ga = *(const float4*)(gw + d * 8);
        float4 gb = *(const float4*)(gw + d * 8 + 4);
        acc[0] += xv * ga.x; acc[1] += xv * ga.y;
        acc[2] += xv * ga.z; acc[3] += xv * ga.w;
        acc[4] += xv * gb.x; acc[5] += xv * gb.y;
        acc[6] += xv * gb.z; acc[7] += xv * gb.w;
    }
#pragma unroll
    for (int e = 0; e < 8; e++)
#pragma unroll
        for (int o = 16; o; o >>= 1) acc[e] += __shfl_xor_sync(0xffffffffu, acc[e], o);
    if (lane == 0) {
        int e0 = 0; float l0 = acc[0];
#pragma unroll
        for (int e = 1; e < 8; e++) if (acc[e] > l0) { l0 = acc[e]; e0 = e; }
        int e1 = 0; float l1 = -3.4e38f;
#pragma unroll
        for (int e = 0; e < 8; e++) if (e != e0 && acc[e] > l1) { l1 = acc[e]; e1 = e; }
        float ex = expf(l1 - l0);
        float inv = 1.f / (1.f + ex);
        g_tok_eid[tok * 2 + 0] = e0;  g_tok_eid[tok * 2 + 1] = e1;
        g_tok_gate[tok * 2 + 0] = inv; g_tok_gate[tok * 2 + 1] = ex * inv;
        atomicAdd(&g_count[e0], 1);
        atomicAdd(&g_count[e1], 1);
    }
}

// ============================================================
// 2) scan: 128-aligned per-expert bases, cursor init, pad fill
// ============================================================
__global__ void k_scan() {
    int base = 0;
    for (int e = 0; e < NEXP; e++) {
        g_pbase[e] = base;
        g_cursor[e] = base;
        int c = g_count[e];
        int p = (c + 127) & ~127;
        for (int s = base + c; s < base + p; s++) { g_slot_tok[s] = 0; g_slot_gate[s] = 0.f; }
        base += p;
    }
    g_pbase[NEXP] = base;
}

// ============================================================
// 3) scatter tokens into compact per-expert slot ranges
// ============================================================
__global__ void k_scatter() {
    int tok = blockIdx.x * 256 + threadIdx.x;
#pragma unroll
    for (int k = 0; k < 2; k++) {
        int e = g_tok_eid[tok * 2 + k];
        int pos = atomicAdd(&g_cursor[e], 1);
        g_slot_tok[pos] = tok;
        g_slot_gate[pos] = g_tok_gate[tok * 2 + k];
    }
}

// ============================================================
// GEMM core: BM=BN=128, BK=16, 256 threads, 8x8 micro-tile
// ============================================================
__device__ __forceinline__ void gemm_main(
    float (*As)[128], float (*Bs)[128],
    const float* __restrict__ a0p, const float* __restrict__ a1p,
    const float* __restrict__ b0p, int ldb, int Kdim,
    float acc[8][8])
{
    int tid = threadIdx.x;
    int r0 = tid >> 2, kk = (tid & 3) << 2;
    int bk = tid >> 5, bn = (tid & 31) << 2;
    int ty = tid >> 4, tx = tid & 15;
    (void)kk; (void)bk; (void)bn;
    for (int k0 = 0; k0 < Kdim; k0 += 16) {
        float4 av0 = *(const float4*)(a0p + k0);
        float4 av1 = *(const float4*)(a1p + k0);
        float4 bv0 = *(const float4*)(b0p + (size_t)k0 * ldb);
        float4 bv1 = *(const float4*)(b0p + (size_t)(k0 + 8) * ldb);
        __syncthreads();
        As[kk + 0][r0] = av0.x; As[kk + 1][r0] = av0.y;
        As[kk + 2][r0] = av0.z; As[kk + 3][r0] = av0.w;
        As[kk + 0][r0 + 64] = av1.x; As[kk + 1][r0 + 64] = av1.y;
        As[kk + 2][r0 + 64] = av1.z; As[kk + 3][r0 + 64] = av1.w;
        *(float4*)&Bs[bk][bn]     = bv0;
        *(float4*)&Bs[bk + 8][bn] = bv1;
        __syncthreads();
#pragma unroll
        for (int k = 0; k < 16; k++) {
            float a[8], b[8];
            *(float4*)&a[0] = *(const float4*)&As[k][ty * 8];
            *(float4*)&a[4] = *(const float4*)&As[k][ty * 8 + 4];
            *(float4*)&b[0] = *(const float4*)&Bs[k][tx * 8];
            *(float4*)&b[4] = *(const float4*)&Bs[k][tx * 8 + 4];
#pragma unroll
            for (int i = 0; i < 8; i++)
#pragma unroll
                for (int j = 0; j < 8; j++)
                    acc[i][j] += a[i] * b[j];
        }
    }
}

__device__ __forceinline__ float gelu_exact(float v) {
    return 0.5f * v * (1.0f + erff(v * 0.70710678118654752f));
}

// ============================================================
// 4) routed GEMM1: h = gelu(gather(x) @ w1[e] + b1[e])
// ============================================================
__global__ void __launch_bounds__(256, 2)
k_gemm1(const float* __restrict__ x, const float* __restrict__ w1,
        const float* __restrict__ b1)
{
    __shared__ float As[16][128], Bs[16][128];
    int row_base = blockIdx.y * 128;
    if (row_base >= g_pbase[NEXP]) return;
    int e = 0;
    while (row_base >= g_pbase[e + 1]) e++;

    int tid = threadIdx.x;
    int r0 = tid >> 2, kk = (tid & 3) << 2;
    int bk = tid >> 5, bn = (tid & 31) << 2;
    int n0 = blockIdx.x * 128;

    int tok0 = g_slot_tok[row_base + r0];
    int tok1 = g_slot_tok[row_base + r0 + 64];
    const float* a0p = x + (size_t)tok0 * DDIM + kk;
    const float* a1p = x + (size_t)tok1 * DDIM + kk;
    const float* b0p = w1 + (size_t)e * DDIM * HDIM + (size_t)bk * HDIM + n0 + bn;

    float acc[8][8] = {};
    gemm_main(As, Bs, a0p, a1p, b0p, HDIM, DDIM, acc);

    int ty = tid >> 4, tx = tid & 15;
    const float* bias = b1 + e * HDIM + n0 + tx * 8;
#pragma unroll
    for (int i = 0; i < 8; i++) {
        size_t r = (size_t)(row_base + ty * 8 + i);
        float* dst = g_hbuf + r * HDIM + n0 + tx * 8;
#pragma unroll
        for (int j = 0; j < 8; j++)
            dst[j] = gelu_exact(acc[i][j] + bias[j]);
    }
}

// ============================================================
// 5) routed GEMM2: out += gate * (h @ w2[e] + b2[e])   (atomic)
// ============================================================
__global__ void __launch_bounds__(256, 2)
k_gemm2(const float* __restrict__ w2, const float* __restrict__ b2,
        float* __restrict__ out)
{
    __shared__ float As[16][128], Bs[16][128];
    int row_base = blockIdx.y * 128;
    if (row_base >= g_pbase[NEXP]) return;
    int e = 0;
    while (row_base >= g_pbase[e + 1]) e++;

    int tid = threadIdx.x;
    int r0 = tid >> 2, kk = (tid & 3) << 2;
    int bk = tid >> 5, bn = (tid & 31) << 2;
    int n0 = blockIdx.x * 128;

    const float* a0p = g_hbuf + (size_t)(row_base + r0) * HDIM + kk;
    const float* a1p = g_hbuf + (size_t)(row_base + r0 + 64) * HDIM + kk;
    const float* b0p = w2 + (size_t)e * HDIM * DDIM + (size_t)bk * DDIM + n0 + bn;

    float acc[8][8] = {};
    gemm_main(As, Bs, a0p, a1p, b0p, DDIM, HDIM, acc);

    int ty = tid >> 4, tx = tid & 15;
    const float* bias = b2 + e * DDIM + n0 + tx * 8;
#pragma unroll
    for (int i = 0; i < 8; i++) {
        int r = row_base + ty * 8 + i;
        float g = g_slot_gate[r];
        if (g != 0.f) {
            int t = g_slot_tok[r];
            float* dst = out + (size_t)t * DDIM + n0 + tx * 8;
#pragma unroll
            for (int j = 0; j < 8; j++)
                atomicAdd(&dst[j], g * (acc[i][j] + bias[j]));
        }
    }
}

// ============================================================
// 6) shared GEMM1: hs = gelu(x @ shared_w1 + shared_b1)
// ============================================================
__global__ void __launch_bounds__(256, 2)
k_shared1(const float* __restrict__ x, const float* __restrict__ sw1,
          const float* __restrict__ sb1)
{
    __shared__ float As[16][128], Bs[16][128];
    int row_base = blockIdx.y * 128;
    int tid = threadIdx.x;
    int r0 = tid >> 2, kk = (tid & 3) << 2;
    int bk = tid >> 5, bn = (tid & 31) << 2;
    int n0 = blockIdx.x * 128;

    const float* a0p = x + (size_t)(row_base + r0) * DDIM + kk;
    const float* a1p = x + (size_t)(row_base + r0 + 64) * DDIM + kk;
    const float* b0p = sw1 + (size_t)bk * SHDIM + n0 + bn;

    float acc[8][8] = {};
    gemm_main(As, Bs, a0p, a1p, b0p, SHDIM, DDIM, acc);

    int ty = tid >> 4, tx = tid & 15;
    const float* bias = sb1 + n0 + tx * 8;
#pragma unroll
    for (int i = 0; i < 8; i++) {
        size_t r = (size_t)(row_base + ty * 8 + i);
        float* dst = g_hs + r * SHDIM + n0 + tx * 8;
#pragma unroll
        for (int j = 0; j < 8; j++)
            dst[j] = gelu_exact(acc[i][j] + bias[j]);
    }
}

// ============================================================
// 7) shared GEMM2: out = hs @ shared_w2 + shared_b2  (init out)
// ============================================================
__global__ void __launch_bounds__(256, 2)
k_shared2(const float* __restrict__ sw2, const float* __restrict__ sb2,
          float* __restrict__ out)
{
    __shared__ float As[16][128], Bs[16][128];
    int row_base = blockIdx.y * 128;
    int tid = threadIdx.x;
    int r0 = tid >> 2, kk = (tid & 3) << 2;
    int bk = tid >> 5, bn = (tid & 31) << 2;
    int n0 = blockIdx.x * 128;

    const float* a0p = g_hs + (size_t)(row_base + r0) * SHDIM + kk;
    const float* a1p = g_hs + (size_t)(row_base + r0 + 64) * SHDIM + kk;
    const float* b0p = sw2 + (size_t)bk * DDIM + n0 + bn;

    float acc[8][8] = {};
    gemm_main(As, Bs, a0p, a1p, b0p, DDIM, SHDIM, acc);

    int ty = tid >> 4, tx = tid & 15;
    const float* bias = sb2 + n0 + tx * 8;
#pragma unroll
    for (int i = 0; i < 8; i++) {
        size_t r = (size_t)(row_base + ty * 8 + i);
        float* dst = out + r * DDIM + n0 + tx * 8;
#pragma unroll
        for (int j = 0; j < 8; j++)
            dst[j] = acc[i][j] + bias[j];
    }
}

// ============================================================
// launch
// ============================================================
extern "C" void kernel_launch(void* const* d_in, const int* in_sizes, int n_in,
                              void* d_out, int out_size)
{
    const float* x   = (const float*)d_in[0];
    const float* gw  = (const float*)d_in[1];
    const float* w1  = (const float*)d_in[2];
    const float* b1  = (const float*)d_in[3];
    const float* w2  = (const float*)d_in[4];
    const float* b2  = (const float*)d_in[5];
    const float* sw1 = (const float*)d_in[6];
    const float* sb1 = (const float*)d_in[7];
    const float* sw2 = (const float*)d_in[8];
    const float* sb2 = (const float*)d_in[9];
    float* out = (float*)d_out;

    k_zero<<<1, 32>>>();
    k_gate<<<NTOK / 8, 256>>>(x, gw);
    k_scan<<<1, 1>>>();
    k_scatter<<<NTOK / 256, 256>>>();

    // routed expert layer 1 (independent of shared path)
    k_gemm1<<<dim3(HDIM / 128, CAP / 128), 256>>>(x, w1, b1);

    // shared experts; k_shared2 initializes out
    k_shared1<<<dim3(SHDIM / 128, NTOK / 128), 256>>>(x, sw1, sb1);
    k_shared2<<<dim3(DDIM / 128, NTOK / 128), 256>>>(sw2, sb2, out);

    // routed expert layer 2, gate-weighted atomic combine into out
    k_gemm2<<<dim3(DDIM / 128, CAP / 128), 256>>>(w2, b2, out);
}

// round 2
// speedup vs baseline: 1.0014x; 1.0014x over previous
#include <cuda_runtime.h>
#include <math.h>

// Problem constants (fixed for this problem instance)
#define NTOK 8192
#define DDIM 2048
#define HDIM 1024
#define NEXP 8
#define SHDIM 2048
#define CAP  17408   // 16384 slots + 8*128 padding headroom

// -------- scratch (device globals: allocation-free) --------
__device__ int   g_count[NEXP];
__device__ int   g_cursor[NEXP];
__device__ int   g_pbase[NEXP + 1];
__device__ int   g_tok_eid[NTOK * 2];
__device__ float g_tok_gate[NTOK * 2];
__device__ int   g_slot_tok[CAP];
__device__ float g_slot_gate[CAP];
__device__ float g_hbuf[(size_t)CAP * HDIM];     // ~71 MB
__device__ float g_hs[(size_t)NTOK * SHDIM];     // ~67 MB

// ============================================================
// 0) zero counters
// ============================================================
__global__ void k_zero() {
    if (threadIdx.x < NEXP) g_count[threadIdx.x] = 0;
}

// ============================================================
// 1) gating: logits = x @ gate_w, top-2, softmax over the 2
//    one warp per token
// ============================================================
__global__ void k_gate(const float* __restrict__ x, const float* __restrict__ gw) {
    int warp = threadIdx.x >> 5;
    int lane = threadIdx.x & 31;
    int tok = blockIdx.x * 8 + warp;
    const float* xr = x + (size_t)tok * DDIM;
    float acc[8] = {0.f,0.f,0.f,0.f,0.f,0.f,0.f,0.f};
    for (int d = lane; d < DDIM; d += 32) {
        float xv = xr[d];
        float4 ga = *(const float4*)(gw + d * 8);
        float4 gb = *(const float4*)(gw + d * 8 + 4);
        acc[0] += xv * ga.x; acc[1] += xv * ga.y;
        acc[2] += xv * ga.z; acc[3] += xv * ga.w;
        acc[4] += xv * gb.x; acc[5] += xv * gb.y;
        acc[6] += xv * gb.z; acc[7] += xv * gb.w;
    }
#pragma unroll
    for (int e = 0; e < 8; e++)
#pragma unroll
        for (int o = 16; o; o >>= 1) acc[e] += __shfl_xor_sync(0xffffffffu, acc[e], o);
    if (lane == 0) {
        int e0 = 0; float l0 = acc[0];
#pragma unroll
        for (int e = 1; e < 8; e++) if (acc[e] > l0) { l0 = acc[e]; e0 = e; }
        int e1 = 0; float l1 = -3.4e38f;
#pragma unroll
        for (int e = 0; e < 8; e++) if (e != e0 && acc[e] > l1) { l1 = acc[e]; e1 = e; }
        float ex = expf(l1 - l0);
        float inv = 1.f / (1.f + ex);
        g_tok_eid[tok * 2 + 0] = e0;  g_tok_eid[tok * 2 + 1] = e1;
        g_tok_gate[tok * 2 + 0] = inv; g_tok_gate[tok * 2 + 1] = ex * inv;
        atomicAdd(&g_count[e0], 1);
        atomicAdd(&g_count[e1], 1);
    }
}

// ============================================================
// 2) scan: 128-aligned per-expert bases, cursor init, pad fill
// ============================================================
__global__ void k_scan() {
    int base = 0;
    for (int e = 0; e < NEXP; e++) {
        g_pbase[e] = base;
        g_cursor[e] = base;
        int c = g_count[e];
        int p = (c + 127) & ~127;
        for (int s = base + c; s < base + p; s++) { g_slot_tok[s] = 0; g_slot_gate[s] = 0.f; }
        base += p;
    }
    g_pbase[NEXP] = base;
}

// ============================================================
// 3) scatter tokens into compact per-expert slot ranges
// ============================================================
__global__ void k_scatter() {
    int tok = blockIdx.x * 256 + threadIdx.x;
#pragma unroll
    for (int k = 0; k < 2; k++) {
        int e = g_tok_eid[tok * 2 + k];
        int pos = atomicAdd(&g_cursor[e], 1);
        g_slot_tok[pos] = tok;
        g_slot_gate[pos] = g_tok_gate[tok * 2 + k];
    }
}

// ============================================================
// GEMM core: BM=BN=128, BK=16, 256 threads, 8x8 micro-tile
// ============================================================
__device__ __forceinline__ void gemm_main(
    float (*As)[128], float (*Bs)[128],
    const float* __restrict__ a0p, const float* __restrict__ a1p,
    const float* __restrict__ b0p, int ldb, int Kdim,
    float acc[8][8])
{
    int tid = threadIdx.x;
    int r0 = tid >> 2, kk = (tid & 3) << 2;
    int bk = tid >> 5, bn = (tid & 31) << 2;
    int ty = tid >> 4, tx = tid & 15;
    (void)kk; (void)bk; (void)bn;
    for (int k0 = 0; k0 < Kdim; k0 += 16) {
        float4 av0 = *(const float4*)(a0p + k0);
        float4 av1 = *(const float4*)(a1p + k0);
        float4 bv0 = *(const float4*)(b0p + (size_t)k0 * ldb);
        float4 bv1 = *(const float4*)(b0p + (size_t)(k0 + 8) * ldb);
        __syncthreads();
        As[kk + 0][r0] = av0.x; As[kk + 1][r0] = av0.y;
        As[kk + 2][r0] = av0.z; As[kk + 3][r0] = av0.w;
        As[kk + 0][r0 + 64] = av1.x; As[kk + 1][r0 + 64] = av1.y;
        As[kk + 2][r0 + 64] = av1.z; As[kk + 3][r0 + 64] = av1.w;
        *(float4*)&Bs[bk][bn]     = bv0;
        *(float4*)&Bs[bk + 8][bn] = bv1;
        __syncthreads();
#pragma unroll
        for (int k = 0; k < 16; k++) {
            float a[8], b[8];
            *(float4*)&a[0] = *(const float4*)&As[k][ty * 8];
            *(float4*)&a[4] = *(const float4*)&As[k][ty * 8 + 4];
            *(float4*)&b[0] = *(const float4*)&Bs[k][tx * 8];
            *(float4*)&b[4] = *(const float4*)&Bs[k][tx * 8 + 4];
#pragma unroll
            for (int i = 0; i < 8; i++)
#pragma unroll
                for (int j = 0; j < 8; j++)
                    acc[i][j] += a[i] * b[j];
        }
    }
}

__device__ __forceinline__ float gelu_exact(float v) {
    return 0.5f * v * (1.0f + erff(v * 0.70710678118654752f));
}

// ============================================================
// 4) routed GEMM1: h = gelu(gather(x) @ w1[e] + b1[e])
// ============================================================
__global__ void __launch_bounds__(256, 2)
k_gemm1(const float* __restrict__ x, const float* __restrict__ w1,
        const float* __restrict__ b1)
{
    __shared__ float As[16][128], Bs[16][128];
    int row_base = blockIdx.y * 128;
    if (row_base >= g_pbase[NEXP]) return;
    int e = 0;
    while (row_base >= g_pbase[e + 1]) e++;

    int tid = threadIdx.x;
    int r0 = tid >> 2, kk = (tid & 3) << 2;
    int bk = tid >> 5, bn = (tid & 31) << 2;
    int n0 = blockIdx.x * 128;

    int tok0 = g_slot_tok[row_base + r0];
    int tok1 = g_slot_tok[row_base + r0 + 64];
    const float* a0p = x + (size_t)tok0 * DDIM + kk;
    const float* a1p = x + (size_t)tok1 * DDIM + kk;
    const float* b0p = w1 + (size_t)e * DDIM * HDIM + (size_t)bk * HDIM + n0 + bn;

    float acc[8][8] = {};
    gemm_main(As, Bs, a0p, a1p, b0p, HDIM, DDIM, acc);

    int ty = tid >> 4, tx = tid & 15;
    const float* bias = b1 + e * HDIM + n0 + tx * 8;
#pragma unroll
    for (int i = 0; i < 8; i++) {
        size_t r = (size_t)(row_base + ty * 8 + i);
        float* dst = g_hbuf + r * HDIM + n0 + tx * 8;
#pragma unroll
        for (int j = 0; j < 8; j++)
            dst[j] = gelu_exact(acc[i][j] + bias[j]);
    }
}

// ============================================================
// 5) routed GEMM2: out += gate * (h @ w2[e] + b2[e])   (atomic)
// ============================================================
__global__ void __launch_bounds__(256, 2)
k_gemm2(const float* __restrict__ w2, const float* __restrict__ b2,
        float* __restrict__ out)
{
    __shared__ float As[16][128], Bs[16][128];
    int row_base = blockIdx.y * 128;
    if (row_base >= g_pbase[NEXP]) return;
    int e = 0;
    while (row_base >= g_pbase[e + 1]) e++;

    int tid = threadIdx.x;
    int r0 = tid >> 2, kk = (tid & 3) << 2;
    int bk = tid >> 5, bn = (tid & 31) << 2;
    int n0 = blockIdx.x * 128;

    const float* a0p = g_hbuf + (size_t)(row_base + r0) * HDIM + kk;
    const float* a1p = g_hbuf + (size_t)(row_base + r0 + 64) * HDIM + kk;
    const float* b0p = w2 + (size_t)e * HDIM * DDIM + (size_t)bk * DDIM + n0 + bn;

    float acc[8][8] = {};
    gemm_main(As, Bs, a0p, a1p, b0p, DDIM, HDIM, acc);

    int ty = tid >> 4, tx = tid & 15;
    const float* bias = b2 + e * DDIM + n0 + tx * 8;
#pragma unroll
    for (int i = 0; i < 8; i++) {
        int r = row_base + ty * 8 + i;
        float g = g_slot_gate[r];
        if (g != 0.f) {
            int t = g_slot_tok[r];
            float* dst = out + (size_t)t * DDIM + n0 + tx * 8;
#pragma unroll
            for (int j = 0; j < 8; j++)
                atomicAdd(&dst[j], g * (acc[i][j] + bias[j]));
        }
    }
}

// ============================================================
// 6) shared GEMM1: hs = gelu(x @ shared_w1 + shared_b1)
// ============================================================
__global__ void __launch_bounds__(256, 2)
k_shared1(const float* __restrict__ x, const float* __restrict__ sw1,
          const float* __restrict__ sb1)
{
    __shared__ float As[16][128], Bs[16][128];
    int row_base = blockIdx.y * 128;
    int tid = threadIdx.x;
    int r0 = tid >> 2, kk = (tid & 3) << 2;
    int bk = tid >> 5, bn = (tid & 31) << 2;
    int n0 = blockIdx.x * 128;

    const float* a0p = x + (size_t)(row_base + r0) * DDIM + kk;
    const float* a1p = x + (size_t)(row_base + r0 + 64) * DDIM + kk;
    const float* b0p = sw1 + (size_t)bk * SHDIM + n0 + bn;

    float acc[8][8] = {};
    gemm_main(As, Bs, a0p, a1p, b0p, SHDIM, DDIM, acc);

    int ty = tid >> 4, tx = tid & 15;
    const float* bias = sb1 + n0 + tx * 8;
#pragma unroll
    for (int i = 0; i < 8; i++) {
        size_t r = (size_t)(row_base + ty * 8 + i);
        float* dst = g_hs + r * SHDIM + n0 + tx * 8;
#pragma unroll
        for (int j = 0; j < 8; j++)
            dst[j] = gelu_exact(acc[i][j] + bias[j]);
    }
}

// ============================================================
// 7) shared GEMM2: out = hs @ shared_w2 + shared_b2  (init out)
// ============================================================
__global__ void __launch_bounds__(256, 2)
k_shared2(const float* __restrict__ sw2, const float* __restrict__ sb2,
          float* __restrict__ out)
{
    __shared__ float As[16][128], Bs[16][128];
    int row_base = blockIdx.y * 128;
    int tid = threadIdx.x;
    int r0 = tid >> 2, kk = (tid & 3) << 2;
    int bk = tid >> 5, bn = (tid & 31) << 2;
    int n0 = blockIdx.x * 128;

    const float* a0p = g_hs + (size_t)(row_base + r0) * SHDIM + kk;
    const float* a1p = g_hs + (size_t)(row_base + r0 + 64) * SHDIM + kk;
    const float* b0p = sw2 + (size_t)bk * DDIM + n0 + bn;

    float acc[8][8] = {};
    gemm_main(As, Bs, a0p, a1p, b0p, DDIM, SHDIM, acc);

    int ty = tid >> 4, tx = tid & 15;
    const float* bias = sb2 + n0 + tx * 8;
#pragma unroll
    for (int i = 0; i < 8; i++) {
        size_t r = (size_t)(row_base + ty * 8 + i);
        float* dst = out + r * DDIM + n0 + tx * 8;
#pragma unroll
        for (int j = 0; j < 8; j++)
            dst[j] = acc[i][j] + bias[j];
    }
}

// ============================================================
// launch
// ============================================================
extern "C" void kernel_launch(void* const* d_in, const int* in_sizes, int n_in,
                              void* d_out, int out_size)
{
    const float* x   = (const float*)d_in[0];
    const float* gw  = (const float*)d_in[1];
    const float* w1  = (const float*)d_in[2];
    const float* b1  = (const float*)d_in[3];
    const float* w2  = (const float*)d_in[4];
    const float* b2  = (const float*)d_in[5];
    const float* sw1 = (const float*)d_in[6];
    const float* sb1 = (const float*)d_in[7];
    const float* sw2 = (const float*)d_in[8];
    const float* sb2 = (const float*)d_in[9];
    float* out = (float*)d_out;

    k_zero<<<1, 32>>>();
    k_gate<<<NTOK / 8, 256>>>(x, gw);
    k_scan<<<1, 1>>>();
    k_scatter<<<NTOK / 256, 256>>>();

    // routed expert layer 1 (independent of shared path)
    k_gemm1<<<dim3(HDIM / 128, CAP / 128), 256>>>(x, w1, b1);

    // shared experts; k_shared2 initializes out
    k_shared1<<<dim3(SHDIM / 128, NTOK / 128), 256>>>(x, sw1, sb1);
    k_shared2<<<dim3(DDIM / 128, NTOK / 128), 256>>>(sw2, sb2, out);

    // routed expert layer 2, gate-weighted atomic combine into out
    k_gemm2<<<dim3(DDIM / 128, CAP / 128), 256>>>(w2, b2, out);
}

// round 4
// speedup vs baseline: 2.3699x; 2.3665x over previous
#include <cuda_runtime.h>
#include <cuda_bf16.h>
#include <math.h>
#include <stdint.h>

// ---------------- problem constants ----------------
#define NTOK 8192
#define DDIM 2048
#define HDIM 1024
#define NEXP 8
#define SHDIM 2048
#define CAP  17408   // 16384 slots + 8*128 pad headroom

// ---------------- scratch (device globals) ----------------
__device__ int   g_count[NEXP];
__device__ int   g_cursor[NEXP];
__device__ int   g_pbase[NEXP + 1];
__device__ int   g_tok_eid[NTOK * 2];
__device__ float g_tok_gate[NTOK * 2];
__device__ int   g_tok_slot[NTOK * 2];
__device__ int   g_slot_tok[CAP];
__device__ float g_slot_gate[CAP];

__device__ float g_hbuf[(size_t)CAP * HDIM];    // routed hidden (fp32)
__device__ float g_hs[(size_t)NTOK * SHDIM];    // shared hidden (fp32)
__device__ float g_sbuf[(size_t)CAP * DDIM];    // gate-scaled routed out per slot

// ---------------- helpers ----------------
__device__ __forceinline__ uint32_t smem_u32(const void* p) {
    uint32_t a;
    asm("{ .reg .u64 t; cvta.to.shared.u64 t, %1; cvt.u32.u64 %0, t; }" : "=r"(a) : "l"(p));
    return a;
}
__device__ __forceinline__ void ldsm4(uint32_t* r, uint32_t addr) {
    asm volatile("ldmatrix.sync.aligned.m8n8.x4.shared.b16 {%0,%1,%2,%3}, [%4];"
                 : "=r"(r[0]), "=r"(r[1]), "=r"(r[2]), "=r"(r[3]) : "r"(addr));
}
__device__ __forceinline__ void ldsm4t(uint32_t* r, uint32_t addr) {
    asm volatile("ldmatrix.sync.aligned.m8n8.x4.trans.shared.b16 {%0,%1,%2,%3}, [%4];"
                 : "=r"(r[0]), "=r"(r[1]), "=r"(r[2]), "=r"(r[3]) : "r"(addr));
}
__device__ __forceinline__ void mma16816(float* c, const uint32_t* a, const uint32_t* b) {
    asm volatile(
        "mma.sync.aligned.m16n8k16.row.col.f32.bf16.bf16.f32 "
        "{%0,%1,%2,%3}, {%4,%5,%6,%7}, {%8,%9}, {%0,%1,%2,%3};"
        : "+f"(c[0]), "+f"(c[1]), "+f"(c[2]), "+f"(c[3])
        : "r"(a[0]), "r"(a[1]), "r"(a[2]), "r"(a[3]), "r"(b[0]), "r"(b[1]));
}
__device__ __forceinline__ float gelu_exact(float v) {
    return 0.5f * v * (1.0f + erff(v * 0.70710678118654752f));
}
__device__ __forceinline__ uint32_t bf2u(__nv_bfloat16 a, __nv_bfloat16 b) {
    return (uint32_t)__bfloat16_as_ushort(a) | ((uint32_t)__bfloat16_as_ushort(b) << 16);
}
// split v -> hi bf16 (packed pairwise) and lo bf16
__device__ __forceinline__ void split4(float4 v, uint2& hi, uint2& lo) {
    __nv_bfloat16 h0 = __float2bfloat16(v.x), h1 = __float2bfloat16(v.y);
    __nv_bfloat16 h2 = __float2bfloat16(v.z), h3 = __float2bfloat16(v.w);
    __nv_bfloat16 l0 = __float2bfloat16(v.x - __bfloat162float(h0));
    __nv_bfloat16 l1 = __float2bfloat16(v.y - __bfloat162float(h1));
    __nv_bfloat16 l2 = __float2bfloat16(v.z - __bfloat162float(h2));
    __nv_bfloat16 l3 = __float2bfloat16(v.w - __bfloat162float(h3));
    hi = make_uint2(bf2u(h0, h1), bf2u(h2, h3));
    lo = make_uint2(bf2u(l0, l1), bf2u(l2, l3));
}

// ============================================================
// prologue kernels (unchanged from the 5964us baseline)
// ============================================================
__global__ void k_zero() { if (threadIdx.x < NEXP) g_count[threadIdx.x] = 0; }

__global__ void k_gate(const float* __restrict__ x, const float* __restrict__ gw) {
    int warp = threadIdx.x >> 5, lane = threadIdx.x & 31;
    int tok = blockIdx.x * 8 + warp;
    const float* xr = x + (size_t)tok * DDIM;
    float acc[8] = {0.f,0.f,0.f,0.f,0.f,0.f,0.f,0.f};
    for (int d = lane; d < DDIM; d += 32) {
        float xv = xr[d];
        float4 ga = *(const float4*)(gw + d * 8);
        float4 gb = *(const float4*)(gw + d * 8 + 4);
        acc[0] += xv * ga.x; acc[1] += xv * ga.y; acc[2] += xv * ga.z; acc[3] += xv * ga.w;
        acc[4] += xv * gb.x; acc[5] += xv * gb.y; acc[6] += xv * gb.z; acc[7] += xv * gb.w;
    }
#pragma unroll
    for (int e = 0; e < 8; e++)
#pragma unroll
        for (int o = 16; o; o >>= 1) acc[e] += __shfl_xor_sync(0xffffffffu, acc[e], o);
    if (lane == 0) {
        int e0 = 0; float l0 = acc[0];
#pragma unroll
        for (int e = 1; e < 8; e++) if (acc[e] > l0) { l0 = acc[e]; e0 = e; }
        int e1 = -1; float l1 = -3.4e38f;
#pragma unroll
        for (int e = 0; e < 8; e++) if (e != e0 && acc[e] > l1) { l1 = acc[e]; e1 = e; }
        float ex = expf(l1 - l0);
        float inv = 1.f / (1.f + ex);
        g_tok_eid[tok*2+0] = e0;  g_tok_eid[tok*2+1] = e1;
        g_tok_gate[tok*2+0] = inv; g_tok_gate[tok*2+1] = ex * inv;
        atomicAdd(&g_count[e0], 1);
        atomicAdd(&g_count[e1], 1);
    }
}

__global__ void k_scan() {
    int base = 0;
    for (int e = 0; e < NEXP; e++) {
        g_pbase[e] = base; g_cursor[e] = base;
        int c = g_count[e];
        int p = (c + 127) & ~127;
        for (int s = base + c; s < base + p; s++) { g_slot_tok[s] = 0; g_slot_gate[s] = 0.f; }
        base += p;
    }
    g_pbase[NEXP] = base;
}

__global__ void k_scatter() {
    int tok = blockIdx.x * 256 + threadIdx.x;
#pragma unroll
    for (int k = 0; k < 2; k++) {
        int e = g_tok_eid[tok*2+k];
        int pos = atomicAdd(&g_cursor[e], 1);
        g_slot_tok[pos] = tok;
        g_slot_gate[pos] = g_tok_gate[tok*2+k];
        g_tok_slot[tok*2+k] = pos;
    }
}

// ============================================================
// HMMA GEMM: tile 128x128, BK=32, 256 threads (8 warps, 2x4),
// warp tile 64x32, mma m16n8k16, bf16 3-product split (on the fly)
// op 0: h    = gelu(gather(x) @ w1[e] + b1[e])      -> g_hbuf
// op 1: sbuf = gate * (h @ w2[e] + b2[e])           -> g_sbuf
// op 2: hs   = gelu(x @ sw1 + sb1)                  -> g_hs
// op 3: out  = hs @ sw2 + sb2                       -> out
// ============================================================
__global__ void __launch_bounds__(256, 2)
k_mma(int op, int K, int ldA, int ldB, int ldO,
      const float* __restrict__ Abase, const float* __restrict__ W,
      const float* __restrict__ bias, float* __restrict__ Obase)
{
    __shared__ __align__(16) __nv_bfloat16 sAh[128 * 40];
    __shared__ __align__(16) __nv_bfloat16 sAl[128 * 40];
    __shared__ __align__(16) __nv_bfloat16 sBh[32 * 136];
    __shared__ __align__(16) __nv_bfloat16 sBl[32 * 136];

    const int tid = threadIdx.x, wid = tid >> 5, lane = tid & 31;
    const int row_base = blockIdx.y * 128;
    const int n0 = blockIdx.x * 128;
    const int routed = (op < 2);

    int e = 0;
    if (routed) {
        if (row_base >= g_pbase[NEXP]) return;
        while (row_base >= g_pbase[e + 1]) e++;
        W    += (size_t)e * K * ldB;
        bias += (size_t)e * ldO;   // ldO == N for both routed ops
    }

    // per-thread A row pointers (4 rows, one per staging pass)
    const float* arow[4];
#pragma unroll
    for (int p = 0; p < 4; p++) {
        int grow = row_base + p * 32 + (tid >> 3);
        if (op == 0) arow[p] = Abase + (size_t)g_slot_tok[grow] * ldA;
        else         arow[p] = Abase + (size_t)grow * ldA;
    }

    const int wm = (wid >> 2) * 64;   // warp M offset
    const int wn = (wid & 3) * 32;    // warp N offset
    const int lm = lane & 15, lh = lane >> 4;

    const uint32_t aAh = smem_u32(sAh), aAl = smem_u32(sAl);
    const uint32_t aBh = smem_u32(sBh), aBl = smem_u32(sBl);

    float acc[4][4][4] = {};

    const int acol = (tid & 7) * 4;          // A staging col
    const int bcol = (tid & 31) * 4;         // B staging col
    const int brow = tid >> 5;               // B staging row (within pass of 8)

    const int nc = K >> 5;
    for (int c = 0; c < nc; c++) {
        int kc = c << 5;
        // global loads (overlap with other warps' compute before the barrier)
        float4 av[4], bv[4];
#pragma unroll
        for (int p = 0; p < 4; p++)
            av[p] = *(const float4*)(arow[p] + kc + acol);
#pragma unroll
        for (int p = 0; p < 4; p++)
            bv[p] = *(const float4*)(W + (size_t)(kc + p * 8 + brow) * ldB + n0 + bcol);

        __syncthreads();   // previous tile consumed
#pragma unroll
        for (int p = 0; p < 4; p++) {
            uint2 hi, lo; split4(av[p], hi, lo);
            int off = (p * 32 + (tid >> 3)) * 40 + acol;
            *(uint2*)(sAh + off) = hi;
            *(uint2*)(sAl + off) = lo;
        }
#pragma unroll
        for (int p = 0; p < 4; p++) {
            uint2 hi, lo; split4(bv[p], hi, lo);
            int off = (p * 8 + brow) * 136 + bcol;
            *(uint2*)(sBh + off) = hi;
            *(uint2*)(sBl + off) = lo;
        }
        __syncthreads();

#pragma unroll
        for (int ks = 0; ks < 2; ks++) {
            int k0 = ks * 16;
            uint32_t af[4][4], bf[2][4];
            // --- Ah x Bh ---
#pragma unroll
            for (int mi = 0; mi < 4; mi++)
                ldsm4(af[mi], aAh + ((wm + mi * 16 + lm) * 40 + k0 + lh * 8) * 2);
#pragma unroll
            for (int np = 0; np < 2; np++)
                ldsm4t(bf[np], aBh + ((k0 + lm) * 136 + wn + np * 16 + lh * 8) * 2);
#pragma unroll
            for (int mi = 0; mi < 4; mi++)
#pragma unroll
                for (int ni = 0; ni < 4; ni++)
                    mma16816(acc[mi][ni], af[mi], &bf[ni >> 1][(ni & 1) * 2]);
            // --- Ah x Bl ---
            uint32_t bf2[2][4];
#pragma unroll
            for (int np = 0; np < 2; np++)
                ldsm4t(bf2[np], aBl + ((k0 + lm) * 136 + wn + np * 16 + lh * 8) * 2);
#pragma unroll
            for (int mi = 0; mi < 4; mi++)
#pragma unroll
                for (int ni = 0; ni < 4; ni++)
                    mma16816(acc[mi][ni], af[mi], &bf2[ni >> 1][(ni & 1) * 2]);
            // --- Al x Bh ---
#pragma unroll
            for (int mi = 0; mi < 4; mi++)
                ldsm4(af[mi], aAl + ((wm + mi * 16 + lm) * 40 + k0 + lh * 8) * 2);
#pragma unroll
            for (int mi = 0; mi < 4; mi++)
#pragma unroll
                for (int ni = 0; ni < 4; ni++)
                    mma16816(acc[mi][ni], af[mi], &bf[ni >> 1][(ni & 1) * 2]);
        }
    }

    // ---------------- epilogue ----------------
#pragma unroll
    for (int mi = 0; mi < 4; mi++) {
#pragma unroll
        for (int ni = 0; ni < 4; ni++) {
            int r = row_base + wm + mi * 16 + (lane >> 2);
            int col = n0 + wn + ni * 8 + (lane & 3) * 2;
            float b0 = bias[col], b1 = bias[col + 1];
#pragma unroll
            for (int half = 0; half < 2; half++) {
                int rr = r + half * 8;
                float v0 = acc[mi][ni][half * 2 + 0] + b0;
                float v1 = acc[mi][ni][half * 2 + 1] + b1;
                if (op == 0 || op == 2) { v0 = gelu_exact(v0); v1 = gelu_exact(v1); }
                else if (op == 1) { float g = g_slot_gate[rr]; v0 *= g; v1 *= g; }
                *(float2*)(Obase + (size_t)rr * ldO + col) = make_float2(v0, v1);
            }
        }
    }
}

// combine: out[tok] += sbuf[slot0] + sbuf[slot1]
__global__ void k_combine(float* __restrict__ out) {
    int tok = blockIdx.x;
    int s0 = g_tok_slot[tok * 2], s1 = g_tok_slot[tok * 2 + 1];
    const float4* a = (const float4*)(g_sbuf + (size_t)s0 * DDIM);
    const float4* b = (const float4*)(g_sbuf + (size_t)s1 * DDIM);
    float4* o = (float4*)(out + (size_t)tok * DDIM);
#pragma unroll
    for (int i = 0; i < 2; i++) {
        int idx = threadIdx.x + i * 256;
        float4 va = a[idx], vb = b[idx], vo = o[idx];
        vo.x += va.x + vb.x; vo.y += va.y + vb.y;
        vo.z += va.z + vb.z; vo.w += va.w + vb.w;
        o[idx] = vo;
    }
}

// ============================================================
// launch
// ============================================================
extern "C" void kernel_launch(void* const* d_in, const int* in_sizes, int n_in,
                              void* d_out, int out_size)
{
    const float* x   = (const float*)d_in[0];
    const float* gw  = (const float*)d_in[1];
    const float* w1  = (const float*)d_in[2];
    const float* b1  = (const float*)d_in[3];
    const float* w2  = (const float*)d_in[4];
    const float* b2  = (const float*)d_in[5];
    const float* sw1 = (const float*)d_in[6];
    const float* sb1 = (const float*)d_in[7];
    const float* sw2 = (const float*)d_in[8];
    const float* sb2 = (const float*)d_in[9];
    float* out = (float*)d_out;

    float* hbuf; cudaGetSymbolAddress((void**)&hbuf, g_hbuf);
    float* hs;   cudaGetSymbolAddress((void**)&hs, g_hs);
    float* sbuf; cudaGetSymbolAddress((void**)&sbuf, g_sbuf);

    k_zero<<<1, 32>>>();
    k_gate<<<NTOK / 8, 256>>>(x, gw);
    k_scan<<<1, 1>>>();
    k_scatter<<<NTOK / 256, 256>>>();

    // routed L1: [CAP,2048] @ [2048,1024]
    k_mma<<<dim3(HDIM / 128, CAP / 128), 256>>>(0, DDIM, DDIM, HDIM, HDIM, x,  w1, b1, hbuf);
    // shared L1: [8192,2048] @ [2048,2048]
    k_mma<<<dim3(SHDIM / 128, NTOK / 128), 256>>>(2, DDIM, DDIM, SHDIM, SHDIM, x, sw1, sb1, hs);
    // shared L2 -> out (initializes out)
    k_mma<<<dim3(DDIM / 128, NTOK / 128), 256>>>(3, SHDIM, SHDIM, DDIM, DDIM, hs, sw2, sb2, out);
    // routed L2 -> sbuf (gate-scaled)
    k_mma<<<dim3(DDIM / 128, CAP / 128), 256>>>(1, HDIM, HDIM, DDIM, DDIM, hbuf, w2, b2, sbuf);

    k_combine<<<NTOK, 256>>>(out);
}

// round 5
// speedup vs baseline: 2.7431x; 1.1575x over previous
#include <cuda_runtime.h>
#include <cuda_bf16.h>
#include <math.h>
#include <stdint.h>

// ---------------- problem constants ----------------
#define NTOK 8192
#define DDIM 2048
#define HDIM 1024
#define NEXP 8
#define SHDIM 2048
#define CAP  17408   // 16384 slots + 8*128 pad headroom

#define DH   (DDIM * HDIM)          // per-expert w1/w2 size
#define SW   (DDIM * SHDIM)         // sw1/sw2 size

// ---------------- scratch (device globals) ----------------
__device__ int   g_count[NEXP];
__device__ int   g_cursor[NEXP];
__device__ int   g_pbase[NEXP + 1];
__device__ int   g_tok_eid[NTOK * 2];
__device__ float g_tok_gate[NTOK * 2];
__device__ int   g_tok_slot[NTOK * 2];
__device__ int   g_slot_tok[CAP];
__device__ float g_slot_gate[CAP];

// bf16 hi/lo planes (hi first, lo second)
__device__ __align__(16) __nv_bfloat16 g_A1[2ull * CAP * DDIM];    // gathered x per slot
__device__ __align__(16) __nv_bfloat16 g_xs[2ull * NTOK * DDIM];   // x natural order
__device__ __align__(16) __nv_bfloat16 g_w1s[2ull * NEXP * DH];    // w1 [e][D][H]
__device__ __align__(16) __nv_bfloat16 g_w2s[2ull * NEXP * DH];    // w2 [e][H][D]
__device__ __align__(16) __nv_bfloat16 g_sw1s[2ull * SW];          // sw1 [D][SH]
__device__ __align__(16) __nv_bfloat16 g_sw2s[2ull * SW];          // sw2 [SH][D]
__device__ __align__(16) __nv_bfloat16 g_h[2ull * CAP * HDIM];     // routed hidden planes
__device__ __align__(16) __nv_bfloat16 g_hs[2ull * NTOK * SHDIM];  // shared hidden planes
__device__ float g_sbuf[(size_t)CAP * DDIM];                       // gate-scaled routed out

// ---------------- helpers ----------------
__device__ __forceinline__ uint32_t smem_u32(const void* p) {
    uint32_t a;
    asm("{ .reg .u64 t; cvta.to.shared.u64 t, %1; cvt.u32.u64 %0, t; }" : "=r"(a) : "l"(p));
    return a;
}
__device__ __forceinline__ void cpa16(uint32_t dst, const void* src) {
    asm volatile("cp.async.cg.shared.global [%0], [%1], 16;" :: "r"(dst), "l"(src));
}
#define CP_COMMIT() asm volatile("cp.async.commit_group;" ::: "memory")
#define CP_WAIT1()  asm volatile("cp.async.wait_group 1;" ::: "memory")
#define CP_WAIT0()  asm volatile("cp.async.wait_group 0;" ::: "memory")

__device__ __forceinline__ void ldsm4(uint32_t* r, uint32_t addr) {
    asm volatile("ldmatrix.sync.aligned.m8n8.x4.shared.b16 {%0,%1,%2,%3}, [%4];"
                 : "=r"(r[0]), "=r"(r[1]), "=r"(r[2]), "=r"(r[3]) : "r"(addr));
}
__device__ __forceinline__ void ldsm4t(uint32_t* r, uint32_t addr) {
    asm volatile("ldmatrix.sync.aligned.m8n8.x4.trans.shared.b16 {%0,%1,%2,%3}, [%4];"
                 : "=r"(r[0]), "=r"(r[1]), "=r"(r[2]), "=r"(r[3]) : "r"(addr));
}
__device__ __forceinline__ void mma16816(float* c, const uint32_t* a, const uint32_t* b) {
    asm volatile(
        "mma.sync.aligned.m16n8k16.row.col.f32.bf16.bf16.f32 "
        "{%0,%1,%2,%3}, {%4,%5,%6,%7}, {%8,%9}, {%0,%1,%2,%3};"
        : "+f"(c[0]), "+f"(c[1]), "+f"(c[2]), "+f"(c[3])
        : "r"(a[0]), "r"(a[1]), "r"(a[2]), "r"(a[3]), "r"(b[0]), "r"(b[1]));
}
__device__ __forceinline__ float gelu_exact(float v) {
    return 0.5f * v * (1.0f + erff(v * 0.70710678118654752f));
}
__device__ __forceinline__ uint32_t bf2u(__nv_bfloat16 a, __nv_bfloat16 b) {
    return (uint32_t)__bfloat16_as_ushort(a) | ((uint32_t)__bfloat16_as_ushort(b) << 16);
}
__device__ __forceinline__ void split4(float4 v, uint2& hi, uint2& lo) {
    __nv_bfloat16 h0 = __float2bfloat16(v.x), h1 = __float2bfloat16(v.y);
    __nv_bfloat16 h2 = __float2bfloat16(v.z), h3 = __float2bfloat16(v.w);
    __nv_bfloat16 l0 = __float2bfloat16(v.x - __bfloat162float(h0));
    __nv_bfloat16 l1 = __float2bfloat16(v.y - __bfloat162float(h1));
    __nv_bfloat16 l2 = __float2bfloat16(v.z - __bfloat162float(h2));
    __nv_bfloat16 l3 = __float2bfloat16(v.w - __bfloat162float(h3));
    hi = make_uint2(bf2u(h0, h1), bf2u(h2, h3));
    lo = make_uint2(bf2u(l0, l1), bf2u(l2, l3));
}

// ============================================================
// prologue kernels
// ============================================================
__global__ void k_zero() { if (threadIdx.x < NEXP) g_count[threadIdx.x] = 0; }

__global__ void k_gate(const float* __restrict__ x, const float* __restrict__ gw) {
    int warp = threadIdx.x >> 5, lane = threadIdx.x & 31;
    int tok = blockIdx.x * 8 + warp;
    const float* xr = x + (size_t)tok * DDIM;
    float acc[8] = {0.f,0.f,0.f,0.f,0.f,0.f,0.f,0.f};
    for (int d = lane; d < DDIM; d += 32) {
        float xv = xr[d];
        float4 ga = *(const float4*)(gw + d * 8);
        float4 gb = *(const float4*)(gw + d * 8 + 4);
        acc[0] += xv * ga.x; acc[1] += xv * ga.y; acc[2] += xv * ga.z; acc[3] += xv * ga.w;
        acc[4] += xv * gb.x; acc[5] += xv * gb.y; acc[6] += xv * gb.z; acc[7] += xv * gb.w;
    }
#pragma unroll
    for (int e = 0; e < 8; e++)
#pragma unroll
        for (int o = 16; o; o >>= 1) acc[e] += __shfl_xor_sync(0xffffffffu, acc[e], o);
    if (lane == 0) {
        int e0 = 0; float l0 = acc[0];
#pragma unroll
        for (int e = 1; e < 8; e++) if (acc[e] > l0) { l0 = acc[e]; e0 = e; }
        int e1 = -1; float l1 = -3.4e38f;
#pragma unroll
        for (int e = 0; e < 8; e++) if (e != e0 && acc[e] > l1) { l1 = acc[e]; e1 = e; }
        float ex = expf(l1 - l0);
        float inv = 1.f / (1.f + ex);
        g_tok_eid[tok*2+0] = e0;  g_tok_eid[tok*2+1] = e1;
        g_tok_gate[tok*2+0] = inv; g_tok_gate[tok*2+1] = ex * inv;
        atomicAdd(&g_count[e0], 1);
        atomicAdd(&g_count[e1], 1);
    }
}

__global__ void k_scan() {
    int base = 0;
    for (int e = 0; e < NEXP; e++) {
        g_pbase[e] = base; g_cursor[e] = base;
        int c = g_count[e];
        int p = (c + 127) & ~127;
        for (int s = base + c; s < base + p; s++) { g_slot_tok[s] = 0; g_slot_gate[s] = 0.f; }
        base += p;
    }
    g_pbase[NEXP] = base;
}

__global__ void k_scatter() {
    int tok = blockIdx.x * 256 + threadIdx.x;
#pragma unroll
    for (int k = 0; k < 2; k++) {
        int e = g_tok_eid[tok*2+k];
        int pos = atomicAdd(&g_cursor[e], 1);
        g_slot_tok[pos] = tok;
        g_slot_gate[pos] = g_tok_gate[tok*2+k];
        g_tok_slot[tok*2+k] = pos;
    }
}

// elementwise fp32 -> bf16 hi/lo planes
__global__ void k_split(const float4* __restrict__ src,
                        __nv_bfloat16* __restrict__ dh,
                        __nv_bfloat16* __restrict__ dl, int n4) {
    int i = blockIdx.x * 256 + threadIdx.x;
    if (i < n4) {
        uint2 hi, lo; split4(src[i], hi, lo);
        *(uint2*)(dh + (size_t)i * 4) = hi;
        *(uint2*)(dl + (size_t)i * 4) = lo;
    }
}

// gather x rows per slot -> g_A1 planes
__global__ void k_gather(const float* __restrict__ x) {
    int slot = blockIdx.x;
    int tok = g_slot_tok[slot];
    const float4* src = (const float4*)(x + (size_t)tok * DDIM);
#pragma unroll
    for (int i = 0; i < 2; i++) {
        int idx = threadIdx.x + i * 256;
        uint2 hi, lo; split4(src[idx], hi, lo);
        size_t o = (size_t)slot * DDIM + idx * 4;
        *(uint2*)(g_A1 + o) = hi;
        *(uint2*)(g_A1 + (size_t)CAP * DDIM + o) = lo;
    }
}

// ============================================================
// HMMA GEMM: tile 128x128, BK=32, 8 warps (2x4), warp tile 64x32,
// bf16 3-product split, cp.async double-buffered, pre-split planes.
// op 0: g_h planes   = gelu(A1 @ w1[e] + b1[e])
// op 1: g_sbuf fp32  = gate * (h @ w2[e] + b2[e])
// op 2: g_hs planes  = gelu(xs @ sw1 + sb1)
// op 3: out fp32     = hs @ sw2 + sb2
// ============================================================
#define STG 37888                                  // bytes per stage
#define OAH 0
#define OAL 10240
#define OBH 20480
#define OBL 29184
#define SMEM_SZ (2 * STG)

extern __shared__ __align__(16) char smem[];

__global__ void __launch_bounds__(256, 2)
k_mma(int op, int K, int ldA, int ldB, int ldO, const float* __restrict__ bias)
{
    const int tid = threadIdx.x, wid = tid >> 5, lane = tid & 31;
    const int row_base = blockIdx.y * 128;
    const int n0 = blockIdx.x * 128;
    const int routed = (op < 2);

    int e = 0;
    if (routed) {
        if (row_base >= g_pbase[NEXP]) return;
        while (row_base >= g_pbase[e + 1]) e++;
        bias += (size_t)e * ldO;
    }

    // operand planes
    const __nv_bfloat16 *Agh, *Agl, *Bgh, *Bgl;
    if (op == 0)      { Agh = g_A1;  Agl = Agh + (size_t)CAP * DDIM;
                        Bgh = g_w1s + (size_t)e * DH; Bgl = Bgh + (size_t)NEXP * DH; }
    else if (op == 1) { Agh = g_h;   Agl = Agh + (size_t)CAP * HDIM;
                        Bgh = g_w2s + (size_t)e * DH; Bgl = Bgh + (size_t)NEXP * DH; }
    else if (op == 2) { Agh = g_xs;  Agl = Agh + (size_t)NTOK * DDIM;
                        Bgh = g_sw1s; Bgl = Bgh + (size_t)SW; }
    else              { Agh = g_hs;  Agl = Agh + (size_t)NTOK * SHDIM;
                        Bgh = g_sw2s; Bgl = Bgh + (size_t)SW; }
    Agh += (size_t)row_base * ldA;
    Agl += (size_t)row_base * ldA;

    const uint32_t sb = smem_u32(smem);

    // staging maps
    const int ar = tid >> 2, ac = (tid & 3) * 8;       // A: 2 chunks/plane (rows ar, ar+64... no: chunk = tid + i*256)
    const int br = tid >> 4, bc = (tid & 15) * 8;      // B: chunk = tid + i*256

    auto load_stage = [&](int c, int s) {
        int kc = c << 5;
        uint32_t st = sb + s * STG;
#pragma unroll
        for (int i = 0; i < 2; i++) {
            int row = ar + i * 64;
            uint32_t d = st + (row * 40 + ac) * 2;
            cpa16(d + OAH, Agh + (size_t)row * ldA + kc + ac);
            cpa16(d + OAL, Agl + (size_t)row * ldA + kc + ac);
        }
#pragma unroll
        for (int i = 0; i < 2; i++) {
            int row = br + i * 16;
            uint32_t d = st + (row * 136 + bc) * 2;
            cpa16(d + OBH, Bgh + (size_t)(kc + row) * ldB + n0 + bc);
            cpa16(d + OBL, Bgl + (size_t)(kc + row) * ldB + n0 + bc);
        }
        CP_COMMIT();
    };

    const int wm = (wid >> 2) * 64;
    const int wn = (wid & 3) * 32;
    const int lm = lane & 15, lh = lane >> 4;

    float acc[4][4][4] = {};

    const int nc = K >> 5;
    load_stage(0, 0);
    for (int c = 0; c < nc; c++) {
        int s = c & 1;
        if (c + 1 < nc) { load_stage(c + 1, s ^ 1); CP_WAIT1(); }
        else            { CP_WAIT0(); }
        __syncthreads();

        uint32_t aAh = sb + s * STG + OAH;
        uint32_t aAl = sb + s * STG + OAL;
        uint32_t aBh = sb + s * STG + OBH;
        uint32_t aBl = sb + s * STG + OBL;
#pragma unroll
        for (int ks = 0; ks < 2; ks++) {
            int k0 = ks * 16;
            uint32_t af[4][4], bf[2][4], bf2[2][4];
#pragma unroll
            for (int mi = 0; mi < 4; mi++)
                ldsm4(af[mi], aAh + ((wm + mi * 16 + lm) * 40 + k0 + lh * 8) * 2);
#pragma unroll
            for (int np = 0; np < 2; np++)
                ldsm4t(bf[np], aBh + ((k0 + lm) * 136 + wn + np * 16 + lh * 8) * 2);
#pragma unroll
            for (int mi = 0; mi < 4; mi++)
#pragma unroll
                for (int ni = 0; ni < 4; ni++)
                    mma16816(acc[mi][ni], af[mi], &bf[ni >> 1][(ni & 1) * 2]);
#pragma unroll
            for (int np = 0; np < 2; np++)
                ldsm4t(bf2[np], aBl + ((k0 + lm) * 136 + wn + np * 16 + lh * 8) * 2);
#pragma unroll
            for (int mi = 0; mi < 4; mi++)
#pragma unroll
                for (int ni = 0; ni < 4; ni++)
                    mma16816(acc[mi][ni], af[mi], &bf2[ni >> 1][(ni & 1) * 2]);
#pragma unroll
            for (int mi = 0; mi < 4; mi++)
                ldsm4(af[mi], aAl + ((wm + mi * 16 + lm) * 40 + k0 + lh * 8) * 2);
#pragma unroll
            for (int mi = 0; mi < 4; mi++)
#pragma unroll
                for (int ni = 0; ni < 4; ni++)
                    mma16816(acc[mi][ni], af[mi], &bf[ni >> 1][(ni & 1) * 2]);
        }
        __syncthreads();
    }

    // ---------------- epilogue ----------------
    __nv_bfloat16 *obh = 0, *obl = 0; float* ofp = 0;
    if (op == 0)      { obh = g_h;  obl = g_h  + (size_t)CAP * HDIM; }
    else if (op == 2) { obh = g_hs; obl = g_hs + (size_t)NTOK * SHDIM; }
    else if (op == 1) { ofp = g_sbuf; }

#pragma unroll
    for (int mi = 0; mi < 4; mi++) {
#pragma unroll
        for (int ni = 0; ni < 4; ni++) {
            int r = row_base + wm + mi * 16 + (lane >> 2);
            int col = n0 + wn + ni * 8 + (lane & 3) * 2;
            float b0 = bias[col], b1 = bias[col + 1];
#pragma unroll
            for (int half = 0; half < 2; half++) {
                int rr = r + half * 8;
                float v0 = acc[mi][ni][half * 2 + 0] + b0;
                float v1 = acc[mi][ni][half * 2 + 1] + b1;
                size_t o = (size_t)rr * ldO + col;
                if (op == 0 || op == 2) {
                    v0 = gelu_exact(v0); v1 = gelu_exact(v1);
                    __nv_bfloat16 h0 = __float2bfloat16(v0);
                    __nv_bfloat16 h1 = __float2bfloat16(v1);
                    __nv_bfloat16 l0 = __float2bfloat16(v0 - __bfloat162float(h0));
                    __nv_bfloat16 l1 = __float2bfloat16(v1 - __bfloat162float(h1));
                    *(uint32_t*)(obh + o) = bf2u(h0, h1);
                    *(uint32_t*)(obl + o) = bf2u(l0, l1);
                } else if (op == 1) {
                    float g = g_slot_gate[rr];
                    *(float2*)(ofp + o) = make_float2(v0 * g, v1 * g);
                }
                // op 3 handled by caller-passed pointer via g_sbuf? -> no: store below
            }
        }
    }
    if (op == 3) {
        // note: op3 writes through ofp==nullptr is impossible; handled here:
    }
}

// op3 variant writing to harness out (separate tiny wrapper to keep k_mma signature clean)
__global__ void __launch_bounds__(256, 2)
k_mma_out(const float* __restrict__ bias, float* __restrict__ out)
{
    const int tid = threadIdx.x, wid = tid >> 5, lane = tid & 31;
    const int row_base = blockIdx.y * 128;
    const int n0 = blockIdx.x * 128;
    const int ldA = SHDIM, ldB = DDIM, ldO = DDIM, K = SHDIM;

    const __nv_bfloat16* Agh = g_hs + (size_t)row_base * ldA;
    const __nv_bfloat16* Agl = g_hs + (size_t)NTOK * SHDIM + (size_t)row_base * ldA;
    const __nv_bfloat16* Bgh = g_sw2s;
    const __nv_bfloat16* Bgl = g_sw2s + (size_t)SW;

    const uint32_t sb = smem_u32(smem);
    const int ar = tid >> 2, ac = (tid & 3) * 8;
    const int br = tid >> 4, bc = (tid & 15) * 8;

    auto load_stage = [&](int c, int s) {
        int kc = c << 5;
        uint32_t st = sb + s * STG;
#pragma unroll
        for (int i = 0; i < 2; i++) {
            int row = ar + i * 64;
            uint32_t d = st + (row * 40 + ac) * 2;
            cpa16(d + OAH, Agh + (size_t)row * ldA + kc + ac);
            cpa16(d + OAL, Agl + (size_t)row * ldA + kc + ac);
        }
#pragma unroll
        for (int i = 0; i < 2; i++) {
            int row = br + i * 16;
            uint32_t d = st + (row * 136 + bc) * 2;
            cpa16(d + OBH, Bgh + (size_t)(kc + row) * ldB + n0 + bc);
            cpa16(d + OBL, Bgl + (size_t)(kc + row) * ldB + n0 + bc);
        }
        CP_COMMIT();
    };

    const int wm = (wid >> 2) * 64, wn = (wid & 3) * 32;
    const int lm = lane & 15, lh = lane >> 4;
    float acc[4][4][4] = {};

    const int nc = K >> 5;
    load_stage(0, 0);
    for (int c = 0; c < nc; c++) {
        int s = c & 1;
        if (c + 1 < nc) { load_stage(c + 1, s ^ 1); CP_WAIT1(); }
        else            { CP_WAIT0(); }
        __syncthreads();
        uint32_t aAh = sb + s * STG + OAH, aAl = sb + s * STG + OAL;
        uint32_t aBh = sb + s * STG + OBH, aBl = sb + s * STG + OBL;
#pragma unroll
        for (int ks = 0; ks < 2; ks++) {
            int k0 = ks * 16;
            uint32_t af[4][4], bf[2][4], bf2[2][4];
#pragma unroll
            for (int mi = 0; mi < 4; mi++)
                ldsm4(af[mi], aAh + ((wm + mi * 16 + lm) * 40 + k0 + lh * 8) * 2);
#pragma unroll
            for (int np = 0; np < 2; np++)
                ldsm4t(bf[np], aBh + ((k0 + lm) * 136 + wn + np * 16 + lh * 8) * 2);
#pragma unroll
            for (int mi = 0; mi < 4; mi++)
#pragma unroll
                for (int ni = 0; ni < 4; ni++)
                    mma16816(acc[mi][ni], af[mi], &bf[ni >> 1][(ni & 1) * 2]);
#pragma unroll
            for (int np = 0; np < 2; np++)
                ldsm4t(bf2[np], aBl + ((k0 + lm) * 136 + wn + np * 16 + lh * 8) * 2);
#pragma unroll
            for (int mi = 0; mi < 4; mi++)
#pragma unroll
                for (int ni = 0; ni < 4; ni++)
                    mma16816(acc[mi][ni], af[mi], &bf2[ni >> 1][(ni & 1) * 2]);
#pragma unroll
            for (int mi = 0; mi < 4; mi++)
                ldsm4(af[mi], aAl + ((wm + mi * 16 + lm) * 40 + k0 + lh * 8) * 2);
#pragma unroll
            for (int mi = 0; mi < 4; mi++)
#pragma unroll
                for (int ni = 0; ni < 4; ni++)
                    mma16816(acc[mi][ni], af[mi], &bf[ni >> 1][(ni & 1) * 2]);
        }
        __syncthreads();
    }
#pragma unroll
    for (int mi = 0; mi < 4; mi++)
#pragma unroll
        for (int ni = 0; ni < 4; ni++) {
            int r = row_base + wm + mi * 16 + (lane >> 2);
            int col = n0 + wn + ni * 8 + (lane & 3) * 2;
            float b0 = bias[col], b1 = bias[col + 1];
#pragma unroll
            for (int half = 0; half < 2; half++) {
                int rr = r + half * 8;
                *(float2*)(out + (size_t)rr * ldO + col) =
                    make_float2(acc[mi][ni][half * 2 + 0] + b0,
                                acc[mi][ni][half * 2 + 1] + b1);
            }
        }
}

// combine: out[tok] += sbuf[slot0] + sbuf[slot1]
__global__ void k_combine(float* __restrict__ out) {
    int tok = blockIdx.x;
    int s0 = g_tok_slot[tok * 2], s1 = g_tok_slot[tok * 2 + 1];
    const float4* a = (const float4*)(g_sbuf + (size_t)s0 * DDIM);
    const float4* b = (const float4*)(g_sbuf + (size_t)s1 * DDIM);
    float4* o = (float4*)(out + (size_t)tok * DDIM);
#pragma unroll
    for (int i = 0; i < 2; i++) {
        int idx = threadIdx.x + i * 256;
        float4 va = a[idx], vb = b[idx], vo = o[idx];
        vo.x += va.x + vb.x; vo.y += va.y + vb.y;
        vo.z += va.z + vb.z; vo.w += va.w + vb.w;
        o[idx] = vo;
    }
}

// ============================================================
// launch
// ============================================================
extern "C" void kernel_launch(void* const* d_in, const int* in_sizes, int n_in,
                              void* d_out, int out_size)
{
    const float* x   = (const float*)d_in[0];
    const float* gw  = (const float*)d_in[1];
    const float* w1  = (const float*)d_in[2];
    const float* b1  = (const float*)d_in[3];
    const float* w2  = (const float*)d_in[4];
    const float* b2  = (const float*)d_in[5];
    const float* sw1 = (const float*)d_in[6];
    const float* sb1 = (const float*)d_in[7];
    const float* sw2 = (const float*)d_in[8];
    const float* sb2 = (const float*)d_in[9];
    float* out = (float*)d_out;

    static int attr_done = 0;
    if (!attr_done) {
        cudaFuncSetAttribute(k_mma, cudaFuncAttributeMaxDynamicSharedMemorySize, SMEM_SZ);
        cudaFuncSetAttribute(k_mma_out, cudaFuncAttributeMaxDynamicSharedMemorySize, SMEM_SZ);
        attr_done = 1;
    }

    __nv_bfloat16 *w1s, *w2s, *sw1s, *sw2s, *xs;
    cudaGetSymbolAddress((void**)&w1s, g_w1s);
    cudaGetSymbolAddress((void**)&w2s, g_w2s);
    cudaGetSymbolAddress((void**)&sw1s, g_sw1s);
    cudaGetSymbolAddress((void**)&sw2s, g_sw2s);
    cudaGetSymbolAddress((void**)&xs, g_xs);

    k_zero<<<1, 32>>>();
    k_gate<<<NTOK / 8, 256>>>(x, gw);
    k_scan<<<1, 1>>>();
    k_scatter<<<NTOK / 256, 256>>>();

    // pre-split planes
    k_split<<<(NEXP * DH / 4 + 255) / 256, 256>>>((const float4*)w1, w1s, w1s + (size_t)NEXP * DH, NEXP * DH / 4);
    k_split<<<(NEXP * DH / 4 + 255) / 256, 256>>>((const float4*)w2, w2s, w2s + (size_t)NEXP * DH, NEXP * DH / 4);
    k_split<<<(SW / 4 + 255) / 256, 256>>>((const float4*)sw1, sw1s, sw1s + (size_t)SW, SW / 4);
    k_split<<<(SW / 4 + 255) / 256, 256>>>((const float4*)sw2, sw2s, sw2s + (size_t)SW, SW / 4);
    k_split<<<((size_t)NTOK * DDIM / 4 + 255) / 256, 256>>>((const float4*)x, xs, xs + (size_t)NTOK * DDIM, NTOK * DDIM / 4);
    k_gather<<<CAP, 256>>>(x);

    // GEMMs
    k_mma<<<dim3(HDIM / 128, CAP / 128), 256, SMEM_SZ>>>(0, DDIM, DDIM, HDIM, HDIM, b1);
    k_mma<<<dim3(SHDIM / 128, NTOK / 128), 256, SMEM_SZ>>>(2, DDIM, DDIM, SHDIM, SHDIM, sb1);
    k_mma_out<<<dim3(DDIM / 128, NTOK / 128), 256, SMEM_SZ>>>(sb2, out);
    k_mma<<<dim3(DDIM / 128, CAP / 128), 256, SMEM_SZ>>>(1, HDIM, HDIM, DDIM, DDIM, b2);

    k_combine<<<NTOK, 256>>>(out);
}